// round 16
// baseline (speedup 1.0000x reference)
#include <cuda_runtime.h>
#include <cuda_fp16.h>
#include <math.h>
#include <stdint.h>

// Problem constants
#define MTOK   8192      // B*S
#define DMODEL 1024
#define DFF    4096
#define SEQ    2048
#define NH     16
#define HD     64
#define LDQKV  3072      // packed q|k|v row stride

// ---------------------------------------------------------------------------
// Scratch (static device globals)
// ---------------------------------------------------------------------------
__device__ float g_x1  [(size_t)MTOK * DMODEL];

__device__ __half g_n1h [(size_t)MTOK * DMODEL];  // LN1 out
__device__ __half g_qkv [(size_t)MTOK * LDQKV];   // QKV out
__device__ __half g_ao  [(size_t)MTOK * DMODEL];  // attention out
__device__ __half g_n2h [(size_t)MTOK * DMODEL];  // LN2 out
__device__ __half g_hh  [(size_t)MTOK * DFF];     // FF1 out

// transposed fp16 weights [N,K]
__device__ __half g_wqkvs[(size_t)LDQKV * DMODEL];
__device__ __half g_wos[(size_t)DMODEL * DMODEL];
__device__ __half g_w1s[(size_t)DFF * DMODEL];
__device__ __half g_w2s[(size_t)DMODEL * DFF];
__device__ float  g_bqkv[LDQKV];

// ---------------------------------------------------------------------------
// PTX helpers (non-'a'-gated: cp.async, ldmatrix, mma.sync)
// ---------------------------------------------------------------------------
__device__ __forceinline__ uint32_t smem_to_u32(const void* p) {
    uint32_t a;
    asm("{ .reg .u64 t; cvta.to.shared.u64 t, %1; cvt.u32.u64 %0, t; }" : "=r"(a) : "l"(p));
    return a;
}
#define CP_ASYNC_CG(dst, src) \
    asm volatile("cp.async.cg.shared.global [%0], [%1], 16;" :: "r"(dst), "l"(src) : "memory")
#define CP_ASYNC_COMMIT() asm volatile("cp.async.commit_group;" ::: "memory")
#define CP_ASYNC_WAIT(n)  asm volatile("cp.async.wait_group %0;" :: "n"(n) : "memory")

#define LDMATRIX_X4(r0, r1, r2, r3, addr) \
    asm volatile("ldmatrix.sync.aligned.m8n8.x4.shared.b16 {%0,%1,%2,%3}, [%4];" \
                 : "=r"(r0), "=r"(r1), "=r"(r2), "=r"(r3) : "r"(addr))

#define LDMATRIX_X4_TRANS(r0, r1, r2, r3, addr) \
    asm volatile("ldmatrix.sync.aligned.m8n8.x4.trans.shared.b16 {%0,%1,%2,%3}, [%4];" \
                 : "=r"(r0), "=r"(r1), "=r"(r2), "=r"(r3) : "r"(addr))

#define MMA_F16(c, a, b) \
    asm volatile("mma.sync.aligned.m16n8k16.row.col.f32.f16.f16.f32 " \
                 "{%0,%1,%2,%3}, {%4,%5,%6,%7}, {%8,%9}, {%0,%1,%2,%3};" \
                 : "+f"((c)[0]), "+f"((c)[1]), "+f"((c)[2]), "+f"((c)[3]) \
                 : "r"((a)[0]), "r"((a)[1]), "r"((a)[2]), "r"((a)[3]), \
                   "r"((b)[0]), "r"((b)[1]))

__device__ __forceinline__ float gelu_exact(float x) {
    return 0.5f * x * (1.0f + erff(x * 0.70710678118654752f));
}
__device__ __forceinline__ uint32_t pack_h2(__half a, __half b) {
    __half2 t; t.x = a; t.y = b;
    return *(uint32_t*)&t;
}

extern __shared__ char dynsmem[];

// ---------------------------------------------------------------------------
// fp16 single-product GEMM: C = A[M,K] @ B[N,K]^T + bias.
// CTA 128x128, 8 warps, K-chunk 64, 3-stage cp.async, 96KB -> 2 CTAs/SM.
// ---------------------------------------------------------------------------
#define BK 64
#define HSTAGE_BYTES 32768
#define HGEMM_SMEM (3 * HSTAGE_BYTES)

__device__ __forceinline__ void issue_stage_h(
    const __half* __restrict__ A, const __half* __restrict__ B,
    int K, int k0, uint32_t stage_base, int tid)
{
    #pragma unroll
    for (int i = 0; i < 8; i++) {
        const int idx  = i * 256 + tid;
        const int tile = idx >> 10;
        const int rem  = idx & 1023;
        const int row  = rem >> 3;
        const int quad = rem & 7;
        const __half* src = (tile ? B : A) + (size_t)row * K + k0 + quad * 8;
        const uint32_t dst = stage_base + tile * 16384 + row * 128 +
                             ((quad ^ (row & 7)) * 16);
        CP_ASYNC_CG(dst, src);
    }
}

template <bool GELU, bool RES, bool HALFOUT>
__global__ __launch_bounds__(256, 2)
void hgemm_kernel(const __half* __restrict__ A, const __half* __restrict__ B,
                  const float* __restrict__ bias, const float* __restrict__ res,
                  float* __restrict__ Cf, __half* __restrict__ Ch,
                  int M, int N, int K)
{
    const uint32_t sb = smem_to_u32(dynsmem);
    const int tid = threadIdx.x;
    const int wid = tid >> 5;
    const int lid = tid & 31;

    const int a0 = blockIdx.y * 128;
    const int b0 = blockIdx.x * 128;
    const int m_w = (wid & 3) * 32;
    const int n_w = (wid >> 2) * 64;

    const __half* Ap = A + (size_t)a0 * K;
    const __half* Bp = B + (size_t)b0 * K;

    const int nch = K / BK;

    #pragma unroll
    for (int s = 0; s < 2; s++) {
        issue_stage_h(Ap, Bp, K, s * BK, sb + s * HSTAGE_BYTES, tid);
        CP_ASYNC_COMMIT();
    }

    float acc[2][8][4];
    #pragma unroll
    for (int i = 0; i < 2; i++)
        #pragma unroll
        for (int j = 0; j < 8; j++)
            #pragma unroll
            for (int c = 0; c < 4; c++) acc[i][j][c] = 0.f;

    const int bA  = lid >> 3;
    const int r8  = lid & 7;
    const int rowA_off = ((bA & 1) * 8) + r8;
    const int qA_off   = bA >> 1;
    const int rowB_off = ((bA >> 1) * 8) + r8;
    const int qB_off   = bA & 1;

    for (int i = 0; i < nch; i++) {
        if (i + 1 < nch) { CP_ASYNC_WAIT(1); } else { CP_ASYNC_WAIT(0); }
        __syncthreads();

        if (i + 2 < nch)
            issue_stage_h(Ap, Bp, K, (i + 2) * BK,
                          sb + ((i + 2) % 3) * HSTAGE_BYTES, tid);
        CP_ASYNC_COMMIT();

        const uint32_t st = sb + (i % 3) * HSTAGE_BYTES;
        const uint32_t sA = st, sB = st + 16384;

        #pragma unroll
        for (int ks = 0; ks < 4; ks++) {
            const int kq = ks * 2;
            uint32_t ah[2][4], bh[8][2];

            #pragma unroll
            for (int mt = 0; mt < 2; mt++) {
                const int row  = m_w + mt * 16 + rowA_off;
                const int quad = kq + qA_off;
                const uint32_t off = row * 128 + ((quad ^ (row & 7)) * 16);
                LDMATRIX_X4(ah[mt][0], ah[mt][1], ah[mt][2], ah[mt][3], sA + off);
            }
            #pragma unroll
            for (int np = 0; np < 4; np++) {
                const int row  = n_w + np * 16 + rowB_off;
                const int quad = kq + qB_off;
                const uint32_t off = row * 128 + ((quad ^ (row & 7)) * 16);
                LDMATRIX_X4(bh[np * 2][0], bh[np * 2][1], bh[np * 2 + 1][0], bh[np * 2 + 1][1], sB + off);
            }

            #pragma unroll
            for (int mt = 0; mt < 2; mt++)
                #pragma unroll
                for (int nt = 0; nt < 8; nt++)
                    MMA_F16(acc[mt][nt], ah[mt], bh[nt]);
        }
    }

    const int gl  = lid >> 2;
    const int tg  = lid & 3;
    #pragma unroll
    for (int mt = 0; mt < 2; mt++) {
        #pragma unroll
        for (int half = 0; half < 2; half++) {
            const int row = a0 + m_w + mt * 16 + gl + half * 8;
            #pragma unroll
            for (int nt = 0; nt < 8; nt++) {
                const int col = b0 + n_w + nt * 8 + tg * 2;
                float v0 = acc[mt][nt][half * 2 + 0];
                float v1 = acc[mt][nt][half * 2 + 1];
                const float2 bb = *(const float2*)&bias[col];
                v0 += bb.x; v1 += bb.y;
                if (GELU) { v0 = gelu_exact(v0); v1 = gelu_exact(v1); }
                if (RES) {
                    const float2 r2 = *(const float2*)&res[(size_t)row * N + col];
                    v0 += r2.x; v1 += r2.y;
                }
                if (HALFOUT) {
                    *(uint32_t*)&Ch[(size_t)row * N + col] =
                        pack_h2(__float2half(v0), __float2half(v1));
                } else {
                    float2 o; o.x = v0; o.y = v1;
                    *(float2*)&Cf[(size_t)row * N + col] = o;
                }
            }
        }
    }
}

// ---------------------------------------------------------------------------
// fp16 single-product causal flash attention.
// Grid (SEQ/128, NH, B), 8 warps; smem 64KB -> 2 CTAs/SM.
// ---------------------------------------------------------------------------
#define ATTH_SMEM (16384 + 3 * 16384)

__global__ __launch_bounds__(256, 2)
void fattn_kernel(const __half* __restrict__ QKV, __half* __restrict__ O)
{
    const uint32_t sb = smem_to_u32(dynsmem);
    const int tid = threadIdx.x;
    const int wid = tid >> 5;
    const int lid = tid & 31;
    const int qt = gridDim.x - 1 - blockIdx.x;   // heavy tiles first
    const int h = blockIdx.y, b = blockIdx.z;
    const int q0 = qt * 128;
    const size_t base = ((size_t)b * SEQ) * LDQKV + h * HD;

    const uint32_t sQ = sb;
    const int nkt = 2 * qt + 2;

    const int bA  = lid >> 3;
    const int r8  = lid & 7;
    const int rowA_off = ((bA & 1) * 8) + r8;
    const int qA_off   = bA >> 1;
    const int rowB_off = ((bA >> 1) * 8) + r8;
    const int qB_off   = bA & 1;
    const int gl = lid >> 2;
    const int tg = lid & 3;

    #pragma unroll
    for (int i = 0; i < 4; i++) {
        const int idx = i * 256 + tid;
        const int row = idx >> 3, quad = idx & 7;
        const __half* src = QKV + base + (size_t)(q0 + row) * LDQKV + quad * 8;
        const uint32_t dst = sQ + row * 128 + ((quad ^ (row & 7)) * 16);
        CP_ASYNC_CG(dst, src);
    }
    #pragma unroll
    for (int stg = 0; stg < 2; stg++) {
        const uint32_t st = sb + 16384 + stg * 16384;
        const int key0 = stg * 64;
        #pragma unroll
        for (int i = 0; i < 4; i++) {
            const int idx = i * 256 + tid;
            const int tile = idx >> 9;
            const int rem = idx & 511;
            const int row = rem >> 3, quad = rem & 7;
            const __half* src = QKV + base + (tile ? 2048 : 1024) +
                                (size_t)(key0 + row) * LDQKV + quad * 8;
            const uint32_t dst = st + tile * 8192 + row * 128 + ((quad ^ (row & 7)) * 16);
            CP_ASYNC_CG(dst, src);
        }
        CP_ASYNC_COMMIT();
    }

    CP_ASYNC_WAIT(1);
    __syncthreads();

    uint32_t qh[4][4];
    #pragma unroll
    for (int ks = 0; ks < 4; ks++) {
        const int row  = wid * 16 + rowA_off;
        const int quad = ks * 2 + qA_off;
        const uint32_t off = row * 128 + ((quad ^ (row & 7)) * 16);
        LDMATRIX_X4(qh[ks][0], qh[ks][1], qh[ks][2], qh[ks][3], sQ + off);
    }

    float o[8][4];
    #pragma unroll
    for (int d = 0; d < 8; d++)
        #pragma unroll
        for (int c = 0; c < 4; c++) o[d][c] = 0.f;
    float m0 = -1e30f, m1 = -1e30f, l0 = 0.f, l1 = 0.f;

    const int rowg0 = q0 + wid * 16 + gl;
    const int rowg1 = rowg0 + 8;

    for (int kt = 0; kt < nkt; kt++) {
        if (kt > 0) {
            if (kt + 1 < nkt) { CP_ASYNC_WAIT(1); } else { CP_ASYNC_WAIT(0); }
            __syncthreads();
        }
        if (kt + 2 < nkt) {
            const uint32_t st = sb + 16384 + ((kt + 2) % 3) * 16384;
            const int key0 = (kt + 2) * 64;
            #pragma unroll
            for (int i = 0; i < 4; i++) {
                const int idx = i * 256 + tid;
                const int tile = idx >> 9;
                const int rem = idx & 511;
                const int row = rem >> 3, quad = rem & 7;
                const __half* src = QKV + base + (tile ? 2048 : 1024) +
                                    (size_t)(key0 + row) * LDQKV + quad * 8;
                const uint32_t dst = st + tile * 8192 + row * 128 + ((quad ^ (row & 7)) * 16);
                CP_ASYNC_CG(dst, src);
            }
            CP_ASYNC_COMMIT();
        }

        const uint32_t st = sb + 16384 + (kt % 3) * 16384;
        const uint32_t sK = st, sV = st + 8192;

        float p[8][4];
        #pragma unroll
        for (int nt = 0; nt < 8; nt++)
            #pragma unroll
            for (int c = 0; c < 4; c++) p[nt][c] = 0.f;

        #pragma unroll
        for (int ks = 0; ks < 4; ks++) {
            const int kq = ks * 2;
            uint32_t kh[8][2];
            #pragma unroll
            for (int np = 0; np < 4; np++) {
                const int row  = np * 16 + rowB_off;
                const int quad = kq + qB_off;
                const uint32_t off = row * 128 + ((quad ^ (row & 7)) * 16);
                LDMATRIX_X4(kh[np * 2][0], kh[np * 2][1], kh[np * 2 + 1][0], kh[np * 2 + 1][1], sK + off);
            }
            #pragma unroll
            for (int nt = 0; nt < 8; nt++)
                MMA_F16(p[nt], qh[ks], kh[nt]);
        }

        const int kt0 = kt * 64;
        const bool msk = (kt >= nkt - 2);
        float tmax0 = -1e30f, tmax1 = -1e30f;
        #pragma unroll
        for (int nt = 0; nt < 8; nt++) {
            #pragma unroll
            for (int c = 0; c < 4; c++) {
                float v = p[nt][c] * 0.125f;
                if (msk) {
                    const int col = kt0 + nt * 8 + tg * 2 + (c & 1);
                    const int rg  = (c < 2) ? rowg0 : rowg1;
                    if (col > rg) v = -1e30f;
                }
                p[nt][c] = v;
                if (c < 2) tmax0 = fmaxf(tmax0, v); else tmax1 = fmaxf(tmax1, v);
            }
        }
        tmax0 = fmaxf(tmax0, __shfl_xor_sync(0xffffffffu, tmax0, 1));
        tmax0 = fmaxf(tmax0, __shfl_xor_sync(0xffffffffu, tmax0, 2));
        tmax1 = fmaxf(tmax1, __shfl_xor_sync(0xffffffffu, tmax1, 1));
        tmax1 = fmaxf(tmax1, __shfl_xor_sync(0xffffffffu, tmax1, 2));

        const float mn0 = fmaxf(m0, tmax0);
        const float mn1 = fmaxf(m1, tmax1);
        const float cr0 = __expf(m0 - mn0);
        const float cr1 = __expf(m1 - mn1);
        m0 = mn0; m1 = mn1;
        l0 *= cr0; l1 *= cr1;
        #pragma unroll
        for (int d = 0; d < 8; d++) {
            o[d][0] *= cr0; o[d][1] *= cr0;
            o[d][2] *= cr1; o[d][3] *= cr1;
        }
        #pragma unroll
        for (int nt = 0; nt < 8; nt++) {
            p[nt][0] = __expf(p[nt][0] - mn0);
            p[nt][1] = __expf(p[nt][1] - mn0);
            p[nt][2] = __expf(p[nt][2] - mn1);
            p[nt][3] = __expf(p[nt][3] - mn1);
            l0 += p[nt][0] + p[nt][1];
            l1 += p[nt][2] + p[nt][3];
        }

        #pragma unroll
        for (int s = 0; s < 4; s++) {
            uint32_t pa[4];
            pa[0] = pack_h2(__float2half(p[2 * s][0]),     __float2half(p[2 * s][1]));
            pa[1] = pack_h2(__float2half(p[2 * s][2]),     __float2half(p[2 * s][3]));
            pa[2] = pack_h2(__float2half(p[2 * s + 1][0]), __float2half(p[2 * s + 1][1]));
            pa[3] = pack_h2(__float2half(p[2 * s + 1][2]), __float2half(p[2 * s + 1][3]));

            uint32_t vh[8][2];
            const int mi = lid >> 3;
            #pragma unroll
            for (int dp = 0; dp < 4; dp++) {
                const int row  = s * 16 + ((mi & 1) * 8) + r8;
                const int quad = dp * 2 + (mi >> 1);
                const uint32_t off = row * 128 + ((quad ^ (row & 7)) * 16);
                LDMATRIX_X4_TRANS(vh[dp * 2][0], vh[dp * 2][1], vh[dp * 2 + 1][0], vh[dp * 2 + 1][1], sV + off);
            }
            #pragma unroll
            for (int dt = 0; dt < 8; dt++)
                MMA_F16(o[dt], pa, vh[dt]);
        }
    }

    l0 += __shfl_xor_sync(0xffffffffu, l0, 1);
    l0 += __shfl_xor_sync(0xffffffffu, l0, 2);
    l1 += __shfl_xor_sync(0xffffffffu, l1, 1);
    l1 += __shfl_xor_sync(0xffffffffu, l1, 2);
    const float inv0 = 1.0f / l0;
    const float inv1 = 1.0f / l1;

    const size_t tok0 = (size_t)b * SEQ + rowg0;
    const size_t tok1 = tok0 + 8;
    #pragma unroll
    for (int dt = 0; dt < 8; dt++) {
        const int col = h * HD + dt * 8 + tg * 2;
        *(uint32_t*)&O[tok0 * DMODEL + col] =
            pack_h2(__float2half(o[dt][0] * inv0), __float2half(o[dt][1] * inv0));
        *(uint32_t*)&O[tok1 * DMODEL + col] =
            pack_h2(__float2half(o[dt][2] * inv1), __float2half(o[dt][3] * inv1));
    }
}

// ---------------------------------------------------------------------------
// LayerNorm -> fp16 single
// ---------------------------------------------------------------------------
__global__ __launch_bounds__(256)
void ln_half_kernel(const float* __restrict__ x, const float* __restrict__ g,
                    const float* __restrict__ b, __half* __restrict__ oh)
{
    const int row = blockIdx.x;
    const int t   = threadIdx.x;
    const float4 v = ((const float4*)(x + (size_t)row * DMODEL))[t];

    float s  = v.x + v.y + v.z + v.w;
    float ss = v.x * v.x + v.y * v.y + v.z * v.z + v.w * v.w;
    #pragma unroll
    for (int o = 16; o > 0; o >>= 1) {
        s  += __shfl_xor_sync(0xffffffffu, s,  o);
        ss += __shfl_xor_sync(0xffffffffu, ss, o);
    }
    __shared__ float rs[8], rss[8];
    if ((t & 31) == 0) { rs[t >> 5] = s; rss[t >> 5] = ss; }
    __syncthreads();
    if (t < 32) {
        s  = (t < 8) ? rs[t]  : 0.f;
        ss = (t < 8) ? rss[t] : 0.f;
        #pragma unroll
        for (int o = 4; o > 0; o >>= 1) {
            s  += __shfl_xor_sync(0xffffffffu, s,  o);
            ss += __shfl_xor_sync(0xffffffffu, ss, o);
        }
        if (t == 0) { rs[0] = s; rss[0] = ss; }
    }
    __syncthreads();
    const float mu  = rs[0]  * (1.0f / DMODEL);
    const float var = rss[0] * (1.0f / DMODEL) - mu * mu;
    const float inv = rsqrtf(var + 1e-5f);

    const float4 gv = ((const float4*)g)[t];
    const float4 bv = ((const float4*)b)[t];
    float o[4];
    o[0] = (v.x - mu) * inv * gv.x + bv.x;
    o[1] = (v.y - mu) * inv * gv.y + bv.y;
    o[2] = (v.z - mu) * inv * gv.z + bv.z;
    o[3] = (v.w - mu) * inv * gv.w + bv.w;

    uint2 pk;
    pk.x = pack_h2(__float2half(o[0]), __float2half(o[1]));
    pk.y = pack_h2(__float2half(o[2]), __float2half(o[3]));
    ((uint2*)(oh + (size_t)row * DMODEL))[t] = pk;
}

// ---------------------------------------------------------------------------
// Weight prep: fp32 [K,N] -> fp16 [N,K] (tiled transpose)
// ---------------------------------------------------------------------------
__device__ __forceinline__ void htile(const float* __restrict__ W, __half* __restrict__ T,
                                      int K, int N, int bx, int by, int tx, int ty)
{
    __shared__ float tile2[32][33];
    const int kx = by * 32;
    const int nx = bx * 32;

    #pragma unroll
    for (int j = ty; j < 32; j += 8)
        tile2[j][tx] = W[(size_t)(kx + j) * N + nx + tx];
    __syncthreads();

    #pragma unroll
    for (int b = ty; b < 32; b += 8)
        T[(size_t)(nx + b) * K + kx + tx] = __float2half(tile2[tx][b]);
}

// prep1: wq|wk|wv -> packed wqkv fp16 + bias concat
__global__ void prep1_kernel(const float* __restrict__ wq, const float* __restrict__ wk,
                             const float* __restrict__ wv,
                             const float* __restrict__ bq, const float* __restrict__ bk,
                             const float* __restrict__ bv,
                             __half* __restrict__ wqkvs, float* __restrict__ bqkv)
{
    const int id = blockIdx.x;
    const int z  = id >> 10;
    const int t  = id & 1023;
    const int tx = threadIdx.x, ty = threadIdx.y;
    const int tid = ty * 32 + tx;

    const float* W = (z == 0) ? wq : (z == 1) ? wk : wv;
    htile(W, wqkvs + (size_t)z * 1024 * DMODEL, DMODEL, DMODEL, t & 31, t >> 5, tx, ty);

    if (t == 0) {
        const float* src = (z == 0) ? bq : (z == 1) ? bk : bv;
        for (int i = tid; i < 1024; i += 256)
            bqkv[z * 1024 + i] = src[i];
    }
}

// prep2: wo (1024 tiles) | w1 (4096 tiles) | w2 (4096 tiles)
__global__ void prep2_kernel(const float* __restrict__ wo, const float* __restrict__ w1,
                             const float* __restrict__ w2,
                             __half* __restrict__ wos,
                             __half* __restrict__ w1s, __half* __restrict__ w2s)
{
    const int id = blockIdx.x;
    const int tx = threadIdx.x, ty = threadIdx.y;

    if (id < 1024) {
        htile(wo, wos, DMODEL, DMODEL, id & 31, id >> 5, tx, ty);
    } else if (id < 5120) {
        const int t = id - 1024;
        htile(w1, w1s, DMODEL, DFF, t & 127, t >> 7, tx, ty);
    } else {
        const int t = id - 5120;
        htile(w2, w2s, DFF, DMODEL, t & 31, t >> 5, tx, ty);
    }
}

// ---------------------------------------------------------------------------
// Orchestration
// ---------------------------------------------------------------------------
extern "C" void kernel_launch(void* const* d_in, const int* in_sizes, int n_in,
                              void* d_out, int out_size)
{
    const float* x     = (const float*)d_in[0];
    const float* wq    = (const float*)d_in[1];
    const float* bq    = (const float*)d_in[2];
    const float* wk    = (const float*)d_in[3];
    const float* bk    = (const float*)d_in[4];
    const float* wv    = (const float*)d_in[5];
    const float* bv    = (const float*)d_in[6];
    const float* wo    = (const float*)d_in[7];
    const float* bo    = (const float*)d_in[8];
    const float* w1    = (const float*)d_in[9];
    const float* b1    = (const float*)d_in[10];
    const float* w2    = (const float*)d_in[11];
    const float* b2    = (const float*)d_in[12];
    const float* ln1_g = (const float*)d_in[13];
    const float* ln1_b = (const float*)d_in[14];
    const float* ln2_g = (const float*)d_in[15];
    const float* ln2_b = (const float*)d_in[16];
    float* out = (float*)d_out;

    float *x1, *bqkv;
    __half *n1h, *qkv, *ao, *n2h, *hh, *wqkvs, *wos, *w1s, *w2s;
    cudaGetSymbolAddress((void**)&x1,    g_x1);
    cudaGetSymbolAddress((void**)&bqkv,  g_bqkv);
    cudaGetSymbolAddress((void**)&n1h,   g_n1h);
    cudaGetSymbolAddress((void**)&qkv,   g_qkv);
    cudaGetSymbolAddress((void**)&ao,    g_ao);
    cudaGetSymbolAddress((void**)&n2h,   g_n2h);
    cudaGetSymbolAddress((void**)&hh,    g_hh);
    cudaGetSymbolAddress((void**)&wqkvs, g_wqkvs);
    cudaGetSymbolAddress((void**)&wos,   g_wos);
    cudaGetSymbolAddress((void**)&w1s,   g_w1s);
    cudaGetSymbolAddress((void**)&w2s,   g_w2s);

    cudaFuncSetAttribute(fattn_kernel, cudaFuncAttributeMaxDynamicSharedMemorySize, ATTH_SMEM);
    cudaFuncSetAttribute(hgemm_kernel<false, false, true>,
                         cudaFuncAttributeMaxDynamicSharedMemorySize, HGEMM_SMEM);
    cudaFuncSetAttribute(hgemm_kernel<true, false, true>,
                         cudaFuncAttributeMaxDynamicSharedMemorySize, HGEMM_SMEM);
    cudaFuncSetAttribute(hgemm_kernel<false, true, false>,
                         cudaFuncAttributeMaxDynamicSharedMemorySize, HGEMM_SMEM);

    dim3 tb(32, 8);
    prep1_kernel<<<3072, tb>>>(wq, wk, wv, bq, bk, bv, wqkvs, bqkv);
    prep2_kernel<<<9216, tb>>>(wo, w1, w2, wos, w1s, w2s);

    // LN1 -> fp16
    ln_half_kernel<<<MTOK, 256>>>(x, ln1_g, ln1_b, n1h);

    // Fused QKV projection (fp16 single) -> packed fp16
    dim3 gQKV(LDQKV / 128, MTOK / 128);
    hgemm_kernel<false, false, true><<<gQKV, 256, HGEMM_SMEM>>>(
        n1h, wqkvs, bqkv, nullptr, nullptr, qkv, MTOK, LDQKV, DMODEL);

    // Causal flash attention (fp16) -> fp16
    fattn_kernel<<<dim3(SEQ / 128, NH, 4), 256, ATTH_SMEM>>>(qkv, ao);

    // #6: O-projection (fp16) + residual -> fp32
    dim3 gP(DMODEL / 128, MTOK / 128);
    hgemm_kernel<false, true, false><<<gP, 256, HGEMM_SMEM>>>(
        ao, wos, bo, x, x1, nullptr, MTOK, DMODEL, DMODEL);

    // LN2 -> fp16
    ln_half_kernel<<<MTOK, 256>>>(x1, ln2_g, ln2_b, n2h);

    // FF1 (fp16) with GELU -> fp16
    dim3 gF1(DFF / 128, MTOK / 128);
    hgemm_kernel<true, false, true><<<gF1, 256, HGEMM_SMEM>>>(
        n2h, w1s, b1, nullptr, nullptr, hh, MTOK, DFF, DMODEL);

    // FF2 (fp16) + residual -> final fp32 output
    dim3 gF2(DMODEL / 128, MTOK / 128);
    hgemm_kernel<false, true, false><<<gF2, 256, HGEMM_SMEM>>>(
        hh, w2s, b2, x1, out, nullptr, MTOK, DMODEL, DFF);
}

// round 17
// speedup vs baseline: 1.5348x; 1.5348x over previous
#include <cuda_runtime.h>
#include <cuda_fp16.h>
#include <math.h>
#include <stdint.h>

// Problem constants
#define MTOK   8192      // B*S
#define DMODEL 1024
#define DFF    4096
#define SEQ    2048
#define NH     16
#define HD     64
#define LDQKV  3072      // packed q|k|v row stride

// ---------------------------------------------------------------------------
// Scratch (static device globals)
// ---------------------------------------------------------------------------
__device__ float g_x1  [(size_t)MTOK * DMODEL];

__device__ __half g_n1h [(size_t)MTOK * DMODEL];  // LN1 out
__device__ __half g_qkv [(size_t)MTOK * LDQKV];   // QKV out
__device__ __half g_ao  [(size_t)MTOK * DMODEL];  // attention out
__device__ __half g_n2h [(size_t)MTOK * DMODEL];  // LN2 out
__device__ __half g_hh  [(size_t)MTOK * DFF];     // FF1 out

// transposed fp16 weights [N,K]
__device__ __half g_wqkvs[(size_t)LDQKV * DMODEL];
__device__ __half g_wos[(size_t)DMODEL * DMODEL];
__device__ __half g_w1s[(size_t)DFF * DMODEL];
__device__ __half g_w2s[(size_t)DMODEL * DFF];
__device__ float  g_bqkv[LDQKV];

// ---------------------------------------------------------------------------
// PTX helpers (non-'a'-gated: cp.async, ldmatrix, mma.sync)
// ---------------------------------------------------------------------------
__device__ __forceinline__ uint32_t smem_to_u32(const void* p) {
    uint32_t a;
    asm("{ .reg .u64 t; cvta.to.shared.u64 t, %1; cvt.u32.u64 %0, t; }" : "=r"(a) : "l"(p));
    return a;
}
#define CP_ASYNC_CG(dst, src) \
    asm volatile("cp.async.cg.shared.global [%0], [%1], 16;" :: "r"(dst), "l"(src) : "memory")
#define CP_ASYNC_COMMIT() asm volatile("cp.async.commit_group;" ::: "memory")
#define CP_ASYNC_WAIT(n)  asm volatile("cp.async.wait_group %0;" :: "n"(n) : "memory")

#define LDMATRIX_X4(r0, r1, r2, r3, addr) \
    asm volatile("ldmatrix.sync.aligned.m8n8.x4.shared.b16 {%0,%1,%2,%3}, [%4];" \
                 : "=r"(r0), "=r"(r1), "=r"(r2), "=r"(r3) : "r"(addr))

#define LDMATRIX_X4_TRANS(r0, r1, r2, r3, addr) \
    asm volatile("ldmatrix.sync.aligned.m8n8.x4.trans.shared.b16 {%0,%1,%2,%3}, [%4];" \
                 : "=r"(r0), "=r"(r1), "=r"(r2), "=r"(r3) : "r"(addr))

#define MMA_F16(c, a, b) \
    asm volatile("mma.sync.aligned.m16n8k16.row.col.f32.f16.f16.f32 " \
                 "{%0,%1,%2,%3}, {%4,%5,%6,%7}, {%8,%9}, {%0,%1,%2,%3};" \
                 : "+f"((c)[0]), "+f"((c)[1]), "+f"((c)[2]), "+f"((c)[3]) \
                 : "r"((a)[0]), "r"((a)[1]), "r"((a)[2]), "r"((a)[3]), \
                   "r"((b)[0]), "r"((b)[1]))

__device__ __forceinline__ float gelu_exact(float x) {
    return 0.5f * x * (1.0f + erff(x * 0.70710678118654752f));
}
__device__ __forceinline__ uint32_t pack_h2(__half a, __half b) {
    __half2 t; t.x = a; t.y = b;
    return *(uint32_t*)&t;
}

extern __shared__ char dynsmem[];

// ---------------------------------------------------------------------------
// fp16 single-product GEMM: C = A[M,K] @ B[N,K]^T + bias.
// CTA 128x128, 8 warps, K-chunk 64, 3-stage cp.async, 96KB -> 2 CTAs/SM.
// Prefetch issue is split into two halves interleaved with the ks loop to
// smooth LSU/l1tex queue pressure (cross-CTA contention at occ=2).
// ---------------------------------------------------------------------------
#define BK 64
#define HSTAGE_BYTES 32768
#define HGEMM_SMEM (3 * HSTAGE_BYTES)

// half = 0 -> quads 0..3 of each row pair pattern; half = 1 -> quads 4..7.
// Each call issues 4 cp.asyncs per thread (1024 total = half a stage).
__device__ __forceinline__ void issue_stage_h_half(
    const __half* __restrict__ A, const __half* __restrict__ B,
    int K, int k0, uint32_t stage_base, int tid, int hf)
{
    #pragma unroll
    for (int i = 0; i < 4; i++) {
        const int idx  = (hf * 4 + i) * 256 + tid;
        const int tile = idx >> 10;
        const int rem  = idx & 1023;
        const int row  = rem >> 3;
        const int quad = rem & 7;
        const __half* src = (tile ? B : A) + (size_t)row * K + k0 + quad * 8;
        const uint32_t dst = stage_base + tile * 16384 + row * 128 +
                             ((quad ^ (row & 7)) * 16);
        CP_ASYNC_CG(dst, src);
    }
}

template <bool GELU, bool RES, bool HALFOUT>
__global__ __launch_bounds__(256, 2)
void hgemm_kernel(const __half* __restrict__ A, const __half* __restrict__ B,
                  const float* __restrict__ bias, const float* __restrict__ res,
                  float* __restrict__ Cf, __half* __restrict__ Ch,
                  int M, int N, int K)
{
    const uint32_t sb = smem_to_u32(dynsmem);
    const int tid = threadIdx.x;
    const int wid = tid >> 5;
    const int lid = tid & 31;

    const int a0 = blockIdx.y * 128;
    const int b0 = blockIdx.x * 128;
    const int m_w = (wid & 3) * 32;
    const int n_w = (wid >> 2) * 64;

    const __half* Ap = A + (size_t)a0 * K;
    const __half* Bp = B + (size_t)b0 * K;

    const int nch = K / BK;

    #pragma unroll
    for (int s = 0; s < 2; s++) {
        issue_stage_h_half(Ap, Bp, K, s * BK, sb + s * HSTAGE_BYTES, tid, 0);
        issue_stage_h_half(Ap, Bp, K, s * BK, sb + s * HSTAGE_BYTES, tid, 1);
        CP_ASYNC_COMMIT();
    }

    float acc[2][8][4];
    #pragma unroll
    for (int i = 0; i < 2; i++)
        #pragma unroll
        for (int j = 0; j < 8; j++)
            #pragma unroll
            for (int c = 0; c < 4; c++) acc[i][j][c] = 0.f;

    const int bA  = lid >> 3;
    const int r8  = lid & 7;
    const int rowA_off = ((bA & 1) * 8) + r8;
    const int qA_off   = bA >> 1;
    const int rowB_off = ((bA >> 1) * 8) + r8;
    const int qB_off   = bA & 1;

    for (int i = 0; i < nch; i++) {
        if (i + 1 < nch) { CP_ASYNC_WAIT(1); } else { CP_ASYNC_WAIT(0); }
        __syncthreads();

        const bool pf = (i + 2 < nch);
        const uint32_t pst = sb + ((i + 2) % 3) * HSTAGE_BYTES;
        const int pk0 = (i + 2) * BK;

        const uint32_t st = sb + (i % 3) * HSTAGE_BYTES;
        const uint32_t sA = st, sB = st + 16384;

        #pragma unroll
        for (int ks = 0; ks < 4; ks++) {
            // interleave prefetch halves with compute
            if (ks == 0 && pf) issue_stage_h_half(Ap, Bp, K, pk0, pst, tid, 0);
            if (ks == 2 && pf) issue_stage_h_half(Ap, Bp, K, pk0, pst, tid, 1);
            if (ks == 3) CP_ASYNC_COMMIT();

            const int kq = ks * 2;
            uint32_t ah[2][4], bh[8][2];

            #pragma unroll
            for (int mt = 0; mt < 2; mt++) {
                const int row  = m_w + mt * 16 + rowA_off;
                const int quad = kq + qA_off;
                const uint32_t off = row * 128 + ((quad ^ (row & 7)) * 16);
                LDMATRIX_X4(ah[mt][0], ah[mt][1], ah[mt][2], ah[mt][3], sA + off);
            }
            #pragma unroll
            for (int np = 0; np < 4; np++) {
                const int row  = n_w + np * 16 + rowB_off;
                const int quad = kq + qB_off;
                const uint32_t off = row * 128 + ((quad ^ (row & 7)) * 16);
                LDMATRIX_X4(bh[np * 2][0], bh[np * 2][1], bh[np * 2 + 1][0], bh[np * 2 + 1][1], sB + off);
            }

            #pragma unroll
            for (int mt = 0; mt < 2; mt++)
                #pragma unroll
                for (int nt = 0; nt < 8; nt++)
                    MMA_F16(acc[mt][nt], ah[mt], bh[nt]);
        }
    }

    const int gl  = lid >> 2;
    const int tg  = lid & 3;
    #pragma unroll
    for (int mt = 0; mt < 2; mt++) {
        #pragma unroll
        for (int half = 0; half < 2; half++) {
            const int row = a0 + m_w + mt * 16 + gl + half * 8;
            #pragma unroll
            for (int nt = 0; nt < 8; nt++) {
                const int col = b0 + n_w + nt * 8 + tg * 2;
                float v0 = acc[mt][nt][half * 2 + 0];
                float v1 = acc[mt][nt][half * 2 + 1];
                const float2 bb = *(const float2*)&bias[col];
                v0 += bb.x; v1 += bb.y;
                if (GELU) { v0 = gelu_exact(v0); v1 = gelu_exact(v1); }
                if (RES) {
                    const float2 r2 = *(const float2*)&res[(size_t)row * N + col];
                    v0 += r2.x; v1 += r2.y;
                }
                if (HALFOUT) {
                    *(uint32_t*)&Ch[(size_t)row * N + col] =
                        pack_h2(__float2half(v0), __float2half(v1));
                } else {
                    float2 o; o.x = v0; o.y = v1;
                    *(float2*)&Cf[(size_t)row * N + col] = o;
                }
            }
        }
    }
}

// ---------------------------------------------------------------------------
// fp16 single-product causal flash attention.
// Grid (SEQ/128, NH, B), 8 warps; smem 64KB -> 2 CTAs/SM.
// ---------------------------------------------------------------------------
#define ATTH_SMEM (16384 + 3 * 16384)

__global__ __launch_bounds__(256, 2)
void fattn_kernel(const __half* __restrict__ QKV, __half* __restrict__ O)
{
    const uint32_t sb = smem_to_u32(dynsmem);
    const int tid = threadIdx.x;
    const int wid = tid >> 5;
    const int lid = tid & 31;
    const int qt = gridDim.x - 1 - blockIdx.x;   // heavy tiles first
    const int h = blockIdx.y, b = blockIdx.z;
    const int q0 = qt * 128;
    const size_t base = ((size_t)b * SEQ) * LDQKV + h * HD;

    const uint32_t sQ = sb;
    const int nkt = 2 * qt + 2;

    const int bA  = lid >> 3;
    const int r8  = lid & 7;
    const int rowA_off = ((bA & 1) * 8) + r8;
    const int qA_off   = bA >> 1;
    const int rowB_off = ((bA >> 1) * 8) + r8;
    const int qB_off   = bA & 1;
    const int gl = lid >> 2;
    const int tg = lid & 3;

    #pragma unroll
    for (int i = 0; i < 4; i++) {
        const int idx = i * 256 + tid;
        const int row = idx >> 3, quad = idx & 7;
        const __half* src = QKV + base + (size_t)(q0 + row) * LDQKV + quad * 8;
        const uint32_t dst = sQ + row * 128 + ((quad ^ (row & 7)) * 16);
        CP_ASYNC_CG(dst, src);
    }
    #pragma unroll
    for (int stg = 0; stg < 2; stg++) {
        const uint32_t st = sb + 16384 + stg * 16384;
        const int key0 = stg * 64;
        #pragma unroll
        for (int i = 0; i < 4; i++) {
            const int idx = i * 256 + tid;
            const int tile = idx >> 9;
            const int rem = idx & 511;
            const int row = rem >> 3, quad = rem & 7;
            const __half* src = QKV + base + (tile ? 2048 : 1024) +
                                (size_t)(key0 + row) * LDQKV + quad * 8;
            const uint32_t dst = st + tile * 8192 + row * 128 + ((quad ^ (row & 7)) * 16);
            CP_ASYNC_CG(dst, src);
        }
        CP_ASYNC_COMMIT();
    }

    CP_ASYNC_WAIT(1);
    __syncthreads();

    uint32_t qh[4][4];
    #pragma unroll
    for (int ks = 0; ks < 4; ks++) {
        const int row  = wid * 16 + rowA_off;
        const int quad = ks * 2 + qA_off;
        const uint32_t off = row * 128 + ((quad ^ (row & 7)) * 16);
        LDMATRIX_X4(qh[ks][0], qh[ks][1], qh[ks][2], qh[ks][3], sQ + off);
    }

    float o[8][4];
    #pragma unroll
    for (int d = 0; d < 8; d++)
        #pragma unroll
        for (int c = 0; c < 4; c++) o[d][c] = 0.f;
    float m0 = -1e30f, m1 = -1e30f, l0 = 0.f, l1 = 0.f;

    const int rowg0 = q0 + wid * 16 + gl;
    const int rowg1 = rowg0 + 8;

    for (int kt = 0; kt < nkt; kt++) {
        if (kt > 0) {
            if (kt + 1 < nkt) { CP_ASYNC_WAIT(1); } else { CP_ASYNC_WAIT(0); }
            __syncthreads();
        }
        if (kt + 2 < nkt) {
            const uint32_t st = sb + 16384 + ((kt + 2) % 3) * 16384;
            const int key0 = (kt + 2) * 64;
            #pragma unroll
            for (int i = 0; i < 4; i++) {
                const int idx = i * 256 + tid;
                const int tile = idx >> 9;
                const int rem = idx & 511;
                const int row = rem >> 3, quad = rem & 7;
                const __half* src = QKV + base + (tile ? 2048 : 1024) +
                                    (size_t)(key0 + row) * LDQKV + quad * 8;
                const uint32_t dst = st + tile * 8192 + row * 128 + ((quad ^ (row & 7)) * 16);
                CP_ASYNC_CG(dst, src);
            }
            CP_ASYNC_COMMIT();
        }

        const uint32_t st = sb + 16384 + (kt % 3) * 16384;
        const uint32_t sK = st, sV = st + 8192;

        float p[8][4];
        #pragma unroll
        for (int nt = 0; nt < 8; nt++)
            #pragma unroll
            for (int c = 0; c < 4; c++) p[nt][c] = 0.f;

        #pragma unroll
        for (int ks = 0; ks < 4; ks++) {
            const int kq = ks * 2;
            uint32_t kh[8][2];
            #pragma unroll
            for (int np = 0; np < 4; np++) {
                const int row  = np * 16 + rowB_off;
                const int quad = kq + qB_off;
                const uint32_t off = row * 128 + ((quad ^ (row & 7)) * 16);
                LDMATRIX_X4(kh[np * 2][0], kh[np * 2][1], kh[np * 2 + 1][0], kh[np * 2 + 1][1], sK + off);
            }
            #pragma unroll
            for (int nt = 0; nt < 8; nt++)
                MMA_F16(p[nt], qh[ks], kh[nt]);
        }

        const int kt0 = kt * 64;
        const bool msk = (kt >= nkt - 2);
        float tmax0 = -1e30f, tmax1 = -1e30f;
        #pragma unroll
        for (int nt = 0; nt < 8; nt++) {
            #pragma unroll
            for (int c = 0; c < 4; c++) {
                float v = p[nt][c] * 0.125f;
                if (msk) {
                    const int col = kt0 + nt * 8 + tg * 2 + (c & 1);
                    const int rg  = (c < 2) ? rowg0 : rowg1;
                    if (col > rg) v = -1e30f;
                }
                p[nt][c] = v;
                if (c < 2) tmax0 = fmaxf(tmax0, v); else tmax1 = fmaxf(tmax1, v);
            }
        }
        tmax0 = fmaxf(tmax0, __shfl_xor_sync(0xffffffffu, tmax0, 1));
        tmax0 = fmaxf(tmax0, __shfl_xor_sync(0xffffffffu, tmax0, 2));
        tmax1 = fmaxf(tmax1, __shfl_xor_sync(0xffffffffu, tmax1, 1));
        tmax1 = fmaxf(tmax1, __shfl_xor_sync(0xffffffffu, tmax1, 2));

        const float mn0 = fmaxf(m0, tmax0);
        const float mn1 = fmaxf(m1, tmax1);
        const float cr0 = __expf(m0 - mn0);
        const float cr1 = __expf(m1 - mn1);
        m0 = mn0; m1 = mn1;
        l0 *= cr0; l1 *= cr1;
        #pragma unroll
        for (int d = 0; d < 8; d++) {
            o[d][0] *= cr0; o[d][1] *= cr0;
            o[d][2] *= cr1; o[d][3] *= cr1;
        }
        #pragma unroll
        for (int nt = 0; nt < 8; nt++) {
            p[nt][0] = __expf(p[nt][0] - mn0);
            p[nt][1] = __expf(p[nt][1] - mn0);
            p[nt][2] = __expf(p[nt][2] - mn1);
            p[nt][3] = __expf(p[nt][3] - mn1);
            l0 += p[nt][0] + p[nt][1];
            l1 += p[nt][2] + p[nt][3];
        }

        #pragma unroll
        for (int s = 0; s < 4; s++) {
            uint32_t pa[4];
            pa[0] = pack_h2(__float2half(p[2 * s][0]),     __float2half(p[2 * s][1]));
            pa[1] = pack_h2(__float2half(p[2 * s][2]),     __float2half(p[2 * s][3]));
            pa[2] = pack_h2(__float2half(p[2 * s + 1][0]), __float2half(p[2 * s + 1][1]));
            pa[3] = pack_h2(__float2half(p[2 * s + 1][2]), __float2half(p[2 * s + 1][3]));

            uint32_t vh[8][2];
            const int mi = lid >> 3;
            #pragma unroll
            for (int dp = 0; dp < 4; dp++) {
                const int row  = s * 16 + ((mi & 1) * 8) + r8;
                const int quad = dp * 2 + (mi >> 1);
                const uint32_t off = row * 128 + ((quad ^ (row & 7)) * 16);
                LDMATRIX_X4_TRANS(vh[dp * 2][0], vh[dp * 2][1], vh[dp * 2 + 1][0], vh[dp * 2 + 1][1], sV + off);
            }
            #pragma unroll
            for (int dt = 0; dt < 8; dt++)
                MMA_F16(o[dt], pa, vh[dt]);
        }
    }

    l0 += __shfl_xor_sync(0xffffffffu, l0, 1);
    l0 += __shfl_xor_sync(0xffffffffu, l0, 2);
    l1 += __shfl_xor_sync(0xffffffffu, l1, 1);
    l1 += __shfl_xor_sync(0xffffffffu, l1, 2);
    const float inv0 = 1.0f / l0;
    const float inv1 = 1.0f / l1;

    const size_t tok0 = (size_t)b * SEQ + rowg0;
    const size_t tok1 = tok0 + 8;
    #pragma unroll
    for (int dt = 0; dt < 8; dt++) {
        const int col = h * HD + dt * 8 + tg * 2;
        *(uint32_t*)&O[tok0 * DMODEL + col] =
            pack_h2(__float2half(o[dt][0] * inv0), __float2half(o[dt][1] * inv0));
        *(uint32_t*)&O[tok1 * DMODEL + col] =
            pack_h2(__float2half(o[dt][2] * inv1), __float2half(o[dt][3] * inv1));
    }
}

// ---------------------------------------------------------------------------
// LayerNorm -> fp16 single
// ---------------------------------------------------------------------------
__global__ __launch_bounds__(256)
void ln_half_kernel(const float* __restrict__ x, const float* __restrict__ g,
                    const float* __restrict__ b, __half* __restrict__ oh)
{
    const int row = blockIdx.x;
    const int t   = threadIdx.x;
    const float4 v = ((const float4*)(x + (size_t)row * DMODEL))[t];

    float s  = v.x + v.y + v.z + v.w;
    float ss = v.x * v.x + v.y * v.y + v.z * v.z + v.w * v.w;
    #pragma unroll
    for (int o = 16; o > 0; o >>= 1) {
        s  += __shfl_xor_sync(0xffffffffu, s,  o);
        ss += __shfl_xor_sync(0xffffffffu, ss, o);
    }
    __shared__ float rs[8], rss[8];
    if ((t & 31) == 0) { rs[t >> 5] = s; rss[t >> 5] = ss; }
    __syncthreads();
    if (t < 32) {
        s  = (t < 8) ? rs[t]  : 0.f;
        ss = (t < 8) ? rss[t] : 0.f;
        #pragma unroll
        for (int o = 4; o > 0; o >>= 1) {
            s  += __shfl_xor_sync(0xffffffffu, s,  o);
            ss += __shfl_xor_sync(0xffffffffu, ss, o);
        }
        if (t == 0) { rs[0] = s; rss[0] = ss; }
    }
    __syncthreads();
    const float mu  = rs[0]  * (1.0f / DMODEL);
    const float var = rss[0] * (1.0f / DMODEL) - mu * mu;
    const float inv = rsqrtf(var + 1e-5f);

    const float4 gv = ((const float4*)g)[t];
    const float4 bv = ((const float4*)b)[t];
    float o[4];
    o[0] = (v.x - mu) * inv * gv.x + bv.x;
    o[1] = (v.y - mu) * inv * gv.y + bv.y;
    o[2] = (v.z - mu) * inv * gv.z + bv.z;
    o[3] = (v.w - mu) * inv * gv.w + bv.w;

    uint2 pk;
    pk.x = pack_h2(__float2half(o[0]), __float2half(o[1]));
    pk.y = pack_h2(__float2half(o[2]), __float2half(o[3]));
    ((uint2*)(oh + (size_t)row * DMODEL))[t] = pk;
}

// ---------------------------------------------------------------------------
// Weight prep: fp32 [K,N] -> fp16 [N,K] (tiled transpose)
// ---------------------------------------------------------------------------
__device__ __forceinline__ void htile(const float* __restrict__ W, __half* __restrict__ T,
                                      int K, int N, int bx, int by, int tx, int ty)
{
    __shared__ float tile2[32][33];
    const int kx = by * 32;
    const int nx = bx * 32;

    #pragma unroll
    for (int j = ty; j < 32; j += 8)
        tile2[j][tx] = W[(size_t)(kx + j) * N + nx + tx];
    __syncthreads();

    #pragma unroll
    for (int b = ty; b < 32; b += 8)
        T[(size_t)(nx + b) * K + kx + tx] = __float2half(tile2[tx][b]);
}

// prep1: wq|wk|wv -> packed wqkv fp16 + bias concat
__global__ void prep1_kernel(const float* __restrict__ wq, const float* __restrict__ wk,
                             const float* __restrict__ wv,
                             const float* __restrict__ bq, const float* __restrict__ bk,
                             const float* __restrict__ bv,
                             __half* __restrict__ wqkvs, float* __restrict__ bqkv)
{
    const int id = blockIdx.x;
    const int z  = id >> 10;
    const int t  = id & 1023;
    const int tx = threadIdx.x, ty = threadIdx.y;
    const int tid = ty * 32 + tx;

    const float* W = (z == 0) ? wq : (z == 1) ? wk : wv;
    htile(W, wqkvs + (size_t)z * 1024 * DMODEL, DMODEL, DMODEL, t & 31, t >> 5, tx, ty);

    if (t == 0) {
        const float* src = (z == 0) ? bq : (z == 1) ? bk : bv;
        for (int i = tid; i < 1024; i += 256)
            bqkv[z * 1024 + i] = src[i];
    }
}

// prep2: wo (1024 tiles) | w1 (4096 tiles) | w2 (4096 tiles)
__global__ void prep2_kernel(const float* __restrict__ wo, const float* __restrict__ w1,
                             const float* __restrict__ w2,
                             __half* __restrict__ wos,
                             __half* __restrict__ w1s, __half* __restrict__ w2s)
{
    const int id = blockIdx.x;
    const int tx = threadIdx.x, ty = threadIdx.y;

    if (id < 1024) {
        htile(wo, wos, DMODEL, DMODEL, id & 31, id >> 5, tx, ty);
    } else if (id < 5120) {
        const int t = id - 1024;
        htile(w1, w1s, DMODEL, DFF, t & 127, t >> 7, tx, ty);
    } else {
        const int t = id - 5120;
        htile(w2, w2s, DFF, DMODEL, t & 31, t >> 5, tx, ty);
    }
}

// ---------------------------------------------------------------------------
// Orchestration
// ---------------------------------------------------------------------------
extern "C" void kernel_launch(void* const* d_in, const int* in_sizes, int n_in,
                              void* d_out, int out_size)
{
    const float* x     = (const float*)d_in[0];
    const float* wq    = (const float*)d_in[1];
    const float* bq    = (const float*)d_in[2];
    const float* wk    = (const float*)d_in[3];
    const float* bk    = (const float*)d_in[4];
    const float* wv    = (const float*)d_in[5];
    const float* bv    = (const float*)d_in[6];
    const float* wo    = (const float*)d_in[7];
    const float* bo    = (const float*)d_in[8];
    const float* w1    = (const float*)d_in[9];
    const float* b1    = (const float*)d_in[10];
    const float* w2    = (const float*)d_in[11];
    const float* b2    = (const float*)d_in[12];
    const float* ln1_g = (const float*)d_in[13];
    const float* ln1_b = (const float*)d_in[14];
    const float* ln2_g = (const float*)d_in[15];
    const float* ln2_b = (const float*)d_in[16];
    float* out = (float*)d_out;

    float *x1, *bqkv;
    __half *n1h, *qkv, *ao, *n2h, *hh, *wqkvs, *wos, *w1s, *w2s;
    cudaGetSymbolAddress((void**)&x1,    g_x1);
    cudaGetSymbolAddress((void**)&bqkv,  g_bqkv);
    cudaGetSymbolAddress((void**)&n1h,   g_n1h);
    cudaGetSymbolAddress((void**)&qkv,   g_qkv);
    cudaGetSymbolAddress((void**)&ao,    g_ao);
    cudaGetSymbolAddress((void**)&n2h,   g_n2h);
    cudaGetSymbolAddress((void**)&hh,    g_hh);
    cudaGetSymbolAddress((void**)&wqkvs, g_wqkvs);
    cudaGetSymbolAddress((void**)&wos,   g_wos);
    cudaGetSymbolAddress((void**)&w1s,   g_w1s);
    cudaGetSymbolAddress((void**)&w2s,   g_w2s);

    cudaFuncSetAttribute(fattn_kernel, cudaFuncAttributeMaxDynamicSharedMemorySize, ATTH_SMEM);
    cudaFuncSetAttribute(hgemm_kernel<false, false, true>,
                         cudaFuncAttributeMaxDynamicSharedMemorySize, HGEMM_SMEM);
    cudaFuncSetAttribute(hgemm_kernel<true, false, true>,
                         cudaFuncAttributeMaxDynamicSharedMemorySize, HGEMM_SMEM);
    cudaFuncSetAttribute(hgemm_kernel<false, true, false>,
                         cudaFuncAttributeMaxDynamicSharedMemorySize, HGEMM_SMEM);

    dim3 tb(32, 8);
    prep1_kernel<<<3072, tb>>>(wq, wk, wv, bq, bk, bv, wqkvs, bqkv);
    prep2_kernel<<<9216, tb>>>(wo, w1, w2, wos, w1s, w2s);

    // LN1 -> fp16
    ln_half_kernel<<<MTOK, 256>>>(x, ln1_g, ln1_b, n1h);

    // Fused QKV projection (fp16 single) -> packed fp16
    dim3 gQKV(LDQKV / 128, MTOK / 128);
    hgemm_kernel<false, false, true><<<gQKV, 256, HGEMM_SMEM>>>(
        n1h, wqkvs, bqkv, nullptr, nullptr, qkv, MTOK, LDQKV, DMODEL);

    // Causal flash attention (fp16) -> fp16
    fattn_kernel<<<dim3(SEQ / 128, NH, 4), 256, ATTH_SMEM>>>(qkv, ao);

    // #6: O-projection (fp16) + residual -> fp32
    dim3 gP(DMODEL / 128, MTOK / 128);
    hgemm_kernel<false, true, false><<<gP, 256, HGEMM_SMEM>>>(
        ao, wos, bo, x, x1, nullptr, MTOK, DMODEL, DMODEL);

    // LN2 -> fp16
    ln_half_kernel<<<MTOK, 256>>>(x1, ln2_g, ln2_b, n2h);

    // FF1 (fp16) with GELU -> fp16
    dim3 gF1(DFF / 128, MTOK / 128);
    hgemm_kernel<true, false, true><<<gF1, 256, HGEMM_SMEM>>>(
        n2h, w1s, b1, nullptr, nullptr, hh, MTOK, DFF, DMODEL);

    // FF2 (fp16) + residual -> final fp32 output
    dim3 gF2(DMODEL / 128, MTOK / 128);
    hgemm_kernel<false, true, false><<<gF2, 256, HGEMM_SMEM>>>(
        hh, w2s, b2, x1, out, nullptr, MTOK, DMODEL, DFF);
}